// round 1
// baseline (speedup 1.0000x reference)
#include <cuda_runtime.h>

#ifndef INPUT_DIM
#define INPUT_DIM 10
#endif

__global__ void __launch_bounds__(256) encoder_gather_kernel(
    const float* __restrict__ x,   // [N, 10]
    const float* __restrict__ t,   // [N, 1]
    const float* __restrict__ y,   // [N, 1]
    const float* __restrict__ w,   // [2048]
    const float* __restrict__ b,   // [2048]
    float* __restrict__ out,       // [N, 1]
    int n)
{
    int i = blockIdx.x * blockDim.x + threadIdx.x;
    if (i >= n) return;

    const float* xr = x + (long long)i * INPUT_DIM;

    // idx = t * 2^10 + sum_j x_j * 2^(9-j)
    int idx = 0;
#pragma unroll
    for (int j = 0; j < INPUT_DIM; ++j) {
        idx = (idx << 1) | (xr[j] > 0.5f ? 1 : 0);
    }
    idx |= (t[i] > 0.5f ? 1 : 0) << INPUT_DIM;

    float wi = __ldg(w + idx);
    float bi = __ldg(b + idx);
    out[i] = fmaf(y[i], wi, bi);
}

extern "C" void kernel_launch(void* const* d_in, const int* in_sizes, int n_in,
                              void* d_out, int out_size)
{
    const float* x = (const float*)d_in[0];
    const float* t = (const float*)d_in[1];
    const float* y = (const float*)d_in[2];
    const float* w = (const float*)d_in[3];
    const float* b = (const float*)d_in[4];
    float* out = (float*)d_out;

    int n = in_sizes[1];  // N rows (t has N elements)

    const int threads = 256;
    int blocks = (n + threads - 1) / threads;
    encoder_gather_kernel<<<blocks, threads>>>(x, t, y, w, b, out, n);
}

// round 2
// speedup vs baseline: 1.1280x; 1.1280x over previous
#include <cuda_runtime.h>

#ifndef INPUT_DIM
#define INPUT_DIM 10
#endif

#define TPB 256
#define SPAD 11   // padded row length in smem (gcd(11,32)=1 -> conflict-free)

__global__ void __launch_bounds__(TPB) encoder_gather_kernel(
    const float* __restrict__ x,   // [N, 10]
    const float* __restrict__ t,   // [N, 1]
    const float* __restrict__ y,   // [N, 1]
    const float* __restrict__ w,   // [2048]
    const float* __restrict__ b,   // [2048]
    float* __restrict__ out,       // [N, 1]
    int n)
{
    __shared__ float sx[TPB * SPAD];

    const int row0 = blockIdx.x * TPB;
    const int nrows = min(TPB, n - row0);

    // ---- Stage x slab [nrows x 10] into smem via coalesced float2 loads ----
    // Slab starts at byte offset row0*40 (multiple of 8 -> float2 ok).
    const float2* __restrict__ x2 =
        (const float2*)(x + (long long)row0 * INPUT_DIM);
    const int nf2 = nrows * (INPUT_DIM / 2);   // 5 float2 per row

    for (int k = threadIdx.x; k < nf2; k += TPB) {
        float2 v = x2[k];
        int f = k * 2;                 // flat float index within slab
        int r = f / INPUT_DIM;         // row within block
        int c = f - r * INPUT_DIM;     // col (even, so c+1 stays in-row)
        sx[r * SPAD + c]     = v.x;
        sx[r * SPAD + c + 1] = v.y;
    }
    __syncthreads();

    const int i = row0 + threadIdx.x;
    if (i >= n) return;

    const float* xr = sx + threadIdx.x * SPAD;

    int idx = 0;
#pragma unroll
    for (int j = 0; j < INPUT_DIM; ++j) {
        idx = (idx << 1) | (xr[j] > 0.5f ? 1 : 0);
    }
    idx |= (t[i] > 0.5f ? 1 : 0) << INPUT_DIM;

    float wi = __ldg(w + idx);
    float bi = __ldg(b + idx);
    out[i] = fmaf(y[i], wi, bi);
}

extern "C" void kernel_launch(void* const* d_in, const int* in_sizes, int n_in,
                              void* d_out, int out_size)
{
    const float* x = (const float*)d_in[0];
    const float* t = (const float*)d_in[1];
    const float* y = (const float*)d_in[2];
    const float* w = (const float*)d_in[3];
    const float* b = (const float*)d_in[4];
    float* out = (float*)d_out;

    int n = in_sizes[1];  // N rows (t has N elements)

    int blocks = (n + TPB - 1) / TPB;
    encoder_gather_kernel<<<blocks, TPB>>>(x, t, y, w, b, out, n);
}

// round 3
// speedup vs baseline: 1.3983x; 1.2397x over previous
#include <cuda_runtime.h>
#include <cstdint>

#define TPB 256
#define RPB 512                 // rows per block (2 per thread)
#define NF  (RPB * 10)          // floats per slab = 5120
#define SMEM_BYTES (NF * 4)     // 20480 B

__global__ void __launch_bounds__(TPB) encoder_kernel(
    const float* __restrict__ x,   // [N,10]
    const float* __restrict__ t,   // [N,1]
    const float* __restrict__ y,   // [N,1]
    const float* __restrict__ w,   // [2048]
    const float* __restrict__ b,   // [2048]
    float* __restrict__ out,       // [N,1]
    int n)
{
    __shared__ float sx[NF];

    const int row0  = blockIdx.x * RPB;
    const int nrows = min(RPB, n - row0);
    const int nf    = nrows * 10;
    const int nf4   = nf >> 2;

    const float* xs = x + (size_t)row0 * 10;
    uint32_t sbase = (uint32_t)__cvta_generic_to_shared(sx);

    // ---- Stage slab via cp.async (L2->SMEM, no register round trip) ----
    #pragma unroll 5
    for (int k = threadIdx.x; k < nf4; k += TPB) {
        uint32_t dst = sbase + k * 16;
        const float4* src = (const float4*)xs + k;
        asm volatile("cp.async.cg.shared.global [%0], [%1], 16;\n"
                     :: "r"(dst), "l"(src));
    }
    // scalar tail if nf not multiple of 4 (generic-n safety)
    for (int k = (nf4 << 2) + threadIdx.x; k < nf; k += TPB)
        sx[k] = xs[k];

    // ---- Early-issue t/y loads for this thread's row pair (overlap) ----
    const int r0 = 2 * threadIdx.x;        // local row
    const int i0 = row0 + r0;              // global row
    float2 tv = make_float2(0.f, 0.f), yv = make_float2(0.f, 0.f);
    const bool full_pair = (i0 + 1 < n);
    if (full_pair) {
        tv = *(const float2*)(t + i0);     // i0 even, 8B aligned
        yv = *(const float2*)(y + i0);
    } else if (i0 < n) {
        tv.x = t[i0];
        yv.x = y[i0];
    }

    asm volatile("cp.async.commit_group;\n");
    asm volatile("cp.async.wait_group 0;\n" ::: "memory");
    __syncthreads();

    if (i0 >= n) return;

    // ---- Read both rows: 20 consecutive floats = 5 x LDS.128, no conflicts ----
    int idx0 = 0, idx1 = 0;
    #pragma unroll
    for (int q = 0; q < 5; ++q) {
        float4 f = *(const float4*)(sx + r0 * 10 + q * 4);
        float e[4] = {f.x, f.y, f.z, f.w};
        #pragma unroll
        for (int c = 0; c < 4; ++c) {
            int fi = 4 * q + c;            // 0..19, compile-time
            int bit = (e[c] != 0.0f) ? 1 : 0;
            if (fi < 10) idx0 = (idx0 << 1) | bit;
            else         idx1 = (idx1 << 1) | bit;
        }
    }
    idx0 |= ((tv.x != 0.0f) ? 1 : 0) << 10;
    idx1 |= ((tv.y != 0.0f) ? 1 : 0) << 10;

    // ---- Gather + FMA (w/b are 8KB each, L1-resident) ----
    float w0 = __ldg(w + idx0), b0 = __ldg(b + idx0);

    if (full_pair) {
        float w1 = __ldg(w + idx1), b1 = __ldg(b + idx1);
        float2 o;
        o.x = fmaf(yv.x, w0, b0);
        o.y = fmaf(yv.y, w1, b1);
        *(float2*)(out + i0) = o;
    } else {
        out[i0] = fmaf(yv.x, w0, b0);
    }
}

extern "C" void kernel_launch(void* const* d_in, const int* in_sizes, int n_in,
                              void* d_out, int out_size)
{
    const float* x = (const float*)d_in[0];
    const float* t = (const float*)d_in[1];
    const float* y = (const float*)d_in[2];
    const float* w = (const float*)d_in[3];
    const float* b = (const float*)d_in[4];
    float* out = (float*)d_out;

    int n = in_sizes[1];
    int blocks = (n + RPB - 1) / RPB;
    encoder_kernel<<<blocks, TPB>>>(x, t, y, w, b, out, n);
}